// round 1
// baseline (speedup 1.0000x reference)
#include <cuda_runtime.h>

#define NN 50000
#define NE 800000
#define NF 512
#define NH 128
#define NC 40

// ---------------- scratch (device globals; no allocation allowed) ----------------
__device__ float g_s1[(size_t)NN * NH];     // x @ W1
__device__ float g_h [(size_t)NN * NH];     // relu(agg1 + b1)
__device__ float g_s2[(size_t)NN * NC];     // h @ W2
__device__ int   g_rowptr[NN + 1];
__device__ int   g_deg[NN];
__device__ int   g_cursor[NN];
__device__ int   g_col[NE];
__device__ float g_val[NE];
__device__ int   g_bsum[64];

// ---------------- helpers ----------------
__device__ __forceinline__ unsigned long long pack2(float x, float y) {
    unsigned long long r;
    asm("mov.b64 %0, {%1, %2};" : "=l"(r) : "f"(x), "f"(y));
    return r;
}
__device__ __forceinline__ void ffma2(unsigned long long& c, unsigned long long a,
                                      unsigned long long b) {
    asm("fma.rn.f32x2 %0, %1, %2, %0;" : "+l"(c) : "l"(a), "l"(b));
}
union U2 { unsigned long long u; float2 f; };

// ---------------- CSR build ----------------
__global__ void k_zero() {
    int i = blockIdx.x * blockDim.x + threadIdx.x;
    if (i < NN) { g_deg[i] = 0; g_cursor[i] = 0; }
}

__global__ void k_count(const int* __restrict__ dst) {
    int e = blockIdx.x * blockDim.x + threadIdx.x;
    if (e < NE) atomicAdd(&g_deg[dst[e]], 1);
}

__global__ void k_blocksum() {
    __shared__ int sh[1024];
    int t = threadIdx.x;
    int i = blockIdx.x * 1024 + t;
    sh[t] = (i < NN) ? g_deg[i] : 0;
    __syncthreads();
    for (int off = 512; off > 0; off >>= 1) {
        if (t < off) sh[t] += sh[t + off];
        __syncthreads();
    }
    if (t == 0) g_bsum[blockIdx.x] = sh[0];
}

__global__ void k_scanbsum() {   // 1 block, 64 threads
    __shared__ int sh[64];
    const int nb = (NN + 1023) / 1024;   // 49
    int t = threadIdx.x;
    int v = (t < nb) ? g_bsum[t] : 0;
    sh[t] = v;
    __syncthreads();
    for (int off = 1; off < 64; off <<= 1) {
        int u = (t >= off) ? sh[t - off] : 0;
        __syncthreads();
        sh[t] += u;
        __syncthreads();
    }
    g_bsum[t] = sh[t] - v;               // exclusive
    if (t == nb - 1) g_rowptr[NN] = sh[t];
}

__global__ void k_scanwrite() {
    __shared__ int sh[1024];
    int t = threadIdx.x;
    int i = blockIdx.x * 1024 + t;
    int v = (i < NN) ? g_deg[i] : 0;
    sh[t] = v;
    __syncthreads();
    for (int off = 1; off < 1024; off <<= 1) {
        int u = (t >= off) ? sh[t - off] : 0;
        __syncthreads();
        sh[t] += u;
        __syncthreads();
    }
    if (i < NN) g_rowptr[i] = g_bsum[blockIdx.x] + sh[t] - v;
}

__global__ void k_fill(const int* __restrict__ src, const int* __restrict__ dst,
                       const float* __restrict__ w) {
    int e = blockIdx.x * blockDim.x + threadIdx.x;
    if (e < NE) {
        int d = dst[e];
        int pos = g_rowptr[d] + atomicAdd(&g_cursor[d], 1);
        g_col[pos] = src[e];
        g_val[pos] = w[e];
    }
}

// ---------------- GEMM1: s1 = x @ W1  (fp32, FFMA2 microkernel) ----------------
// BM=128, BN=128(=NH), BK=16, 256 threads, per-thread 8x8 via 4 row-pairs x 8 cols.
__global__ __launch_bounds__(256) void k_gemm1(const float* __restrict__ x,
                                               const float* __restrict__ W1,
                                               float* __restrict__ s1) {
    __shared__ __align__(16) float As[16][128];
    __shared__ __align__(16) float Bs[16][128];
    const int tid  = threadIdx.x;
    const int m0   = blockIdx.x * 128;
    const int row0 = (tid >> 4) << 3;   // 0..120
    const int col0 = (tid & 15) << 3;   // 0..120

    unsigned long long acc[4][8];
#pragma unroll
    for (int p = 0; p < 4; p++)
#pragma unroll
        for (int c = 0; c < 8; c++) acc[p][c] = 0ull;

    for (int kt = 0; kt < NF; kt += 16) {
        // load A tile (128 rows x 16 k), store transposed As[k][row]
#pragma unroll
        for (int u = 0; u < 2; u++) {
            int fi = tid + u * 256;          // 0..511 (512 float4)
            int r = fi >> 2, c4 = fi & 3;
            int grow = m0 + r;
            float4 v = make_float4(0.f, 0.f, 0.f, 0.f);
            if (grow < NN)
                v = *(const float4*)(x + (size_t)grow * NF + kt + c4 * 4);
            As[c4 * 4 + 0][r] = v.x;
            As[c4 * 4 + 1][r] = v.y;
            As[c4 * 4 + 2][r] = v.z;
            As[c4 * 4 + 3][r] = v.w;
        }
        // load B tile (16 k x 128 n)
#pragma unroll
        for (int u = 0; u < 2; u++) {
            int fi = tid + u * 256;
            int r = fi >> 5, c4 = fi & 31;
            *(float4*)&Bs[r][c4 * 4] =
                *(const float4*)(W1 + (size_t)(kt + r) * NH + c4 * 4);
        }
        __syncthreads();
#pragma unroll
        for (int kk = 0; kk < 16; kk++) {
            float4 a0 = *(const float4*)&As[kk][row0];
            float4 a1 = *(const float4*)&As[kk][row0 + 4];
            unsigned long long ap[4];
            ap[0] = pack2(a0.x, a0.y);
            ap[1] = pack2(a0.z, a0.w);
            ap[2] = pack2(a1.x, a1.y);
            ap[3] = pack2(a1.z, a1.w);
            float4 b0 = *(const float4*)&Bs[kk][col0];
            float4 b1 = *(const float4*)&Bs[kk][col0 + 4];
            float bb[8] = {b0.x, b0.y, b0.z, b0.w, b1.x, b1.y, b1.z, b1.w};
#pragma unroll
            for (int c = 0; c < 8; c++) {
                unsigned long long bp = pack2(bb[c], bb[c]);
#pragma unroll
                for (int p = 0; p < 4; p++) ffma2(acc[p][c], ap[p], bp);
            }
        }
        __syncthreads();
    }
    // epilogue
#pragma unroll
    for (int p = 0; p < 4; p++) {
#pragma unroll
        for (int h = 0; h < 2; h++) {
            int row = m0 + row0 + p * 2 + h;
            if (row < NN) {
                float v[8];
#pragma unroll
                for (int c = 0; c < 8; c++) {
                    U2 u; u.u = acc[p][c];
                    v[c] = h ? u.f.y : u.f.x;
                }
                float4* o = (float4*)(s1 + (size_t)row * NH + col0);
                o[0] = make_float4(v[0], v[1], v[2], v[3]);
                o[1] = make_float4(v[4], v[5], v[6], v[7]);
            }
        }
    }
}

// ---------------- CSR gather aggregation: out[n] = bias + sum_e w*src[col[e]] ----
template <int F4, bool RELU>
__global__ void k_agg(const float* __restrict__ src, const float* __restrict__ bias,
                      float* __restrict__ out) {
    int idx = blockIdx.x * blockDim.x + threadIdx.x;
    int n = idx / F4;
    int f = idx % F4;
    if (n >= NN) return;
    int beg = g_rowptr[n], end = g_rowptr[n + 1];
    const float4* s4 = (const float4*)src;
    float4 acc = make_float4(0.f, 0.f, 0.f, 0.f);
    int e = beg;
    for (; e + 1 < end; e += 2) {
        int   c0 = g_col[e],     c1 = g_col[e + 1];
        float w0 = g_val[e],     w1 = g_val[e + 1];
        float4 v0 = s4[(size_t)c0 * F4 + f];
        float4 v1 = s4[(size_t)c1 * F4 + f];
        acc.x = fmaf(v0.x, w0, acc.x); acc.y = fmaf(v0.y, w0, acc.y);
        acc.z = fmaf(v0.z, w0, acc.z); acc.w = fmaf(v0.w, w0, acc.w);
        acc.x = fmaf(v1.x, w1, acc.x); acc.y = fmaf(v1.y, w1, acc.y);
        acc.z = fmaf(v1.z, w1, acc.z); acc.w = fmaf(v1.w, w1, acc.w);
    }
    if (e < end) {
        int c = g_col[e]; float w = g_val[e];
        float4 v = s4[(size_t)c * F4 + f];
        acc.x = fmaf(v.x, w, acc.x); acc.y = fmaf(v.y, w, acc.y);
        acc.z = fmaf(v.z, w, acc.z); acc.w = fmaf(v.w, w, acc.w);
    }
    float4 b = ((const float4*)bias)[f];
    acc.x += b.x; acc.y += b.y; acc.z += b.z; acc.w += b.w;
    if (RELU) {
        acc.x = fmaxf(acc.x, 0.f); acc.y = fmaxf(acc.y, 0.f);
        acc.z = fmaxf(acc.z, 0.f); acc.w = fmaxf(acc.w, 0.f);
    }
    ((float4*)out)[(size_t)n * F4 + f] = acc;
}

// ---------------- GEMM2: s2 = h @ W2  (W2 in smem, 8x5 microtile) ----------------
__global__ __launch_bounds__(256) void k_gemm2(const float* __restrict__ h,
                                               const float* __restrict__ W2,
                                               float* __restrict__ s2) {
    __shared__ __align__(16) float Ws[NH * NC];       // 128*40 = 20 KB
    __shared__ __align__(16) float Hs[16][264];       // 16 k x 256 rows (+8 pad)
    const int tid = threadIdx.x;
    const int n0  = blockIdx.x * 256;
#pragma unroll
    for (int i = 0; i < 5; i++) {
        int fi = tid + i * 256;                       // 1280 float4
        *(float4*)&Ws[fi * 4] = *(const float4*)(W2 + (size_t)fi * 4);
    }
    const int tc = tid & 7;     // col group 0..7 (5 cols each)
    const int tr = tid >> 3;    // 0..31 (8 rows each)
    const int r0 = tr * 8;
    const int c0 = tc * 5;
    float acc[8][5];
#pragma unroll
    for (int i = 0; i < 8; i++)
#pragma unroll
        for (int j = 0; j < 5; j++) acc[i][j] = 0.f;

    for (int kc = 0; kc < NH; kc += 16) {
        __syncthreads();
#pragma unroll
        for (int i = 0; i < 4; i++) {
            int fi = tid + i * 256;                   // 1024 float4
            int r = fi >> 2, c4 = fi & 3;
            int n = n0 + r;
            float4 v = make_float4(0.f, 0.f, 0.f, 0.f);
            if (n < NN)
                v = *(const float4*)(h + (size_t)n * NH + kc + c4 * 4);
            Hs[c4 * 4 + 0][r] = v.x;
            Hs[c4 * 4 + 1][r] = v.y;
            Hs[c4 * 4 + 2][r] = v.z;
            Hs[c4 * 4 + 3][r] = v.w;
        }
        __syncthreads();
#pragma unroll
        for (int k = 0; k < 16; k++) {
            float4 a0 = *(const float4*)&Hs[k][r0];
            float4 a1 = *(const float4*)&Hs[k][r0 + 4];
            float a[8] = {a0.x, a0.y, a0.z, a0.w, a1.x, a1.y, a1.z, a1.w};
            float w[5];
#pragma unroll
            for (int j = 0; j < 5; j++) w[j] = Ws[(kc + k) * NC + c0 + j];
#pragma unroll
            for (int i = 0; i < 8; i++)
#pragma unroll
                for (int j = 0; j < 5; j++) acc[i][j] = fmaf(a[i], w[j], acc[i][j]);
        }
    }
#pragma unroll
    for (int i = 0; i < 8; i++) {
        int n = n0 + r0 + i;
        if (n < NN) {
#pragma unroll
            for (int j = 0; j < 5; j++) s2[(size_t)n * NC + c0 + j] = acc[i][j];
        }
    }
}

// ---------------- launcher ----------------
extern "C" void kernel_launch(void* const* d_in, const int* in_sizes, int n_in,
                              void* d_out, int out_size) {
    const float* x  = (const float*)d_in[0];
    const int*   es = (const int*)d_in[1];
    const int*   ed = (const int*)d_in[2];
    const float* ew = (const float*)d_in[3];
    const float* W1 = (const float*)d_in[4];
    const float* b1 = (const float*)d_in[5];
    const float* W2 = (const float*)d_in[6];
    const float* b2 = (const float*)d_in[7];
    float* out = (float*)d_out;

    float *s1p, *hp, *s2p;
    cudaGetSymbolAddress((void**)&s1p, g_s1);
    cudaGetSymbolAddress((void**)&hp,  g_h);
    cudaGetSymbolAddress((void**)&s2p, g_s2);

    // CSR build (reused by both layers)
    k_zero<<<(NN + 255) / 256, 256>>>();
    k_count<<<(NE + 255) / 256, 256>>>(ed);
    k_blocksum<<<(NN + 1023) / 1024, 1024>>>();
    k_scanbsum<<<1, 64>>>();
    k_scanwrite<<<(NN + 1023) / 1024, 1024>>>();
    k_fill<<<(NE + 255) / 256, 256>>>(es, ed, ew);

    // layer 1
    k_gemm1<<<(NN + 127) / 128, 256>>>(x, W1, s1p);
    k_agg<32, true><<<(NN * 32 + 255) / 256, 256>>>(s1p, b1, hp);

    // layer 2
    k_gemm2<<<(NN + 255) / 256, 256>>>(hp, W2, s2p);
    k_agg<10, false><<<(NN * 10 + 255) / 256, 256>>>(s2p, b2, out);
}

// round 3
// speedup vs baseline: 1.3907x; 1.3907x over previous
#include <cuda_runtime.h>
#include <cuda_bf16.h>
#include <cstdint>

#define NN 50000
#define NE 800000
#define NF 512
#define NH 128
#define NC 40

// ---------------- scratch (device globals; no allocation allowed) ----------------
__device__ float g_s1[(size_t)NN * NH];     // x @ W1
__device__ float g_h [(size_t)NN * NH];     // relu(agg1 + b1)
__device__ float g_s2[(size_t)NN * NC];     // h @ W2
__device__ int   g_rowptr[NN + 1];
__device__ int   g_deg[NN];
__device__ int   g_cursor[NN];
__device__ int   g_col[NE];
__device__ float g_val[NE];
__device__ int   g_bsum[64];
__device__ __nv_bfloat16 g_w1t_hi[(size_t)NH * NF];   // W1^T hi: [n][k]
__device__ __nv_bfloat16 g_w1t_lo[(size_t)NH * NF];   // W1^T lo: [n][k]

// ---------------- PTX helpers (portable: sm_80-level only) ----------------
__device__ __forceinline__ uint32_t smem_u32(const void* p) {
    uint32_t a;
    asm("{ .reg .u64 t; cvta.to.shared.u64 t, %1; cvt.u32.u64 %0, t; }"
        : "=r"(a) : "l"(p));
    return a;
}
__device__ __forceinline__ void ldsm_x4(uint32_t* r, uint32_t addr) {
    asm volatile("ldmatrix.sync.aligned.m8n8.x4.shared.b16 {%0,%1,%2,%3}, [%4];"
                 : "=r"(r[0]), "=r"(r[1]), "=r"(r[2]), "=r"(r[3]) : "r"(addr));
}
__device__ __forceinline__ void ldsm_x2(uint32_t* r, uint32_t addr) {
    asm volatile("ldmatrix.sync.aligned.m8n8.x2.shared.b16 {%0,%1}, [%2];"
                 : "=r"(r[0]), "=r"(r[1]) : "r"(addr));
}
__device__ __forceinline__ void mma_bf16(float* c, const uint32_t* a, const uint32_t* b) {
    asm volatile(
        "mma.sync.aligned.m16n8k16.row.col.f32.bf16.bf16.f32 "
        "{%0,%1,%2,%3}, {%4,%5,%6,%7}, {%8,%9}, {%0,%1,%2,%3};"
        : "+f"(c[0]), "+f"(c[1]), "+f"(c[2]), "+f"(c[3])
        : "r"(a[0]), "r"(a[1]), "r"(a[2]), "r"(a[3]), "r"(b[0]), "r"(b[1]));
}

// ---------------- CSR build ----------------
__global__ void k_zero() {
    int i = blockIdx.x * blockDim.x + threadIdx.x;
    if (i < NN) { g_deg[i] = 0; g_cursor[i] = 0; }
}
__global__ void k_count(const int* __restrict__ dst) {
    int e = blockIdx.x * blockDim.x + threadIdx.x;
    if (e < NE) atomicAdd(&g_deg[dst[e]], 1);
}
__global__ void k_blocksum() {
    __shared__ int sh[1024];
    int t = threadIdx.x;
    int i = blockIdx.x * 1024 + t;
    sh[t] = (i < NN) ? g_deg[i] : 0;
    __syncthreads();
    for (int off = 512; off > 0; off >>= 1) {
        if (t < off) sh[t] += sh[t + off];
        __syncthreads();
    }
    if (t == 0) g_bsum[blockIdx.x] = sh[0];
}
__global__ void k_scanbsum() {
    __shared__ int sh[64];
    const int nb = (NN + 1023) / 1024;
    int t = threadIdx.x;
    int v = (t < nb) ? g_bsum[t] : 0;
    sh[t] = v;
    __syncthreads();
    for (int off = 1; off < 64; off <<= 1) {
        int u = (t >= off) ? sh[t - off] : 0;
        __syncthreads();
        sh[t] += u;
        __syncthreads();
    }
    g_bsum[t] = sh[t] - v;
    if (t == nb - 1) g_rowptr[NN] = sh[t];
}
__global__ void k_scanwrite() {
    __shared__ int sh[1024];
    int t = threadIdx.x;
    int i = blockIdx.x * 1024 + t;
    int v = (i < NN) ? g_deg[i] : 0;
    sh[t] = v;
    __syncthreads();
    for (int off = 1; off < 1024; off <<= 1) {
        int u = (t >= off) ? sh[t - off] : 0;
        __syncthreads();
        sh[t] += u;
        __syncthreads();
    }
    if (i < NN) g_rowptr[i] = g_bsum[blockIdx.x] + sh[t] - v;
}
__global__ void k_fill(const int* __restrict__ src, const int* __restrict__ dst,
                       const float* __restrict__ w) {
    int e = blockIdx.x * blockDim.x + threadIdx.x;
    if (e < NE) {
        int d = dst[e];
        int pos = g_rowptr[d] + atomicAdd(&g_cursor[d], 1);
        g_col[pos] = src[e];
        g_val[pos] = w[e];
    }
}

// ---------------- W1 transpose + hi/lo split ----------------
__global__ void k_w1split(const float* __restrict__ W1) {
    int idx = blockIdx.x * blockDim.x + threadIdx.x;   // over NF*NH
    if (idx < NF * NH) {
        int k = idx >> 7;       // row of W1
        int n = idx & 127;      // col of W1
        float v = W1[idx];
        __nv_bfloat16 hi = __float2bfloat16(v);
        float r = v - __bfloat162float(hi);
        __nv_bfloat16 lo = __float2bfloat16(r);
        g_w1t_hi[(size_t)n * NF + k] = hi;
        g_w1t_lo[(size_t)n * NF + k] = lo;
    }
}

// ---------------- GEMM1: s1 = x @ W1 via mma.sync bf16 split (3 MMA) ----------
// CTA tile M=128 x N=128, BK=64, 256 threads = 8 warps (2m x 4n), warp 64x32.
// SMEM rows padded to 72 bf16 (144B) -> conflict-free ldmatrix.
#define BK      64
#define NCHUNK  (NF / BK)          // 8
#define LDA     72                 // bf16 elems per smem row (144 B)
#define PLANE   (128 * LDA * 2)    // 18432 B
#define SA_HI   0
#define SA_LO   PLANE
#define SB_HI   (2 * PLANE)
#define SB_LO   (3 * PLANE)
#define SMEM_SZ (4 * PLANE)        // 73728 B

__global__ __launch_bounds__(256) void k_gemm1_mma(const float* __restrict__ x,
                                                   float* __restrict__ s1) {
    extern __shared__ __align__(16) char smem[];
    const uint32_t sb = smem_u32(smem);
    const int tid = threadIdx.x;
    const int lane = tid & 31;
    const int wid = tid >> 5;
    const int wm = wid >> 2;          // 0..1   (64 rows each)
    const int wn = wid & 3;           // 0..3   (32 cols each)
    const int m0 = blockIdx.x * 128;

    const __nv_bfloat16* __restrict__ Bhi = g_w1t_hi;
    const __nv_bfloat16* __restrict__ Blo = g_w1t_lo;

    float acc[4][4][4];
#pragma unroll
    for (int i = 0; i < 4; i++)
#pragma unroll
        for (int j = 0; j < 4; j++)
#pragma unroll
            for (int q = 0; q < 4; q++) acc[i][j][q] = 0.f;

    // lane-fixed ldmatrix address bases
    const uint32_t a_base = sb + SA_HI +
        (uint32_t)(wm * 64 + (lane & 15)) * (LDA * 2) + (uint32_t)((lane >> 4) * 16);
    const uint32_t b_base = sb + SB_HI +
        (uint32_t)(wn * 32 + (lane & 7)) * (LDA * 2) + (uint32_t)(((lane >> 3) & 1) * 16);

    for (int c = 0; c < NCHUNK; c++) {
        if (c > 0) __syncthreads();   // protect smem reuse
        // ---- A tile: 128 rows x 64 k, fp32 -> bf16 hi/lo ----
#pragma unroll
        for (int it = 0; it < 8; it++) {
            int idx = it * 256 + tid;          // 0..2047
            int r = idx >> 4, c4 = idx & 15;
            int row = m0 + r;
            float4 v = make_float4(0.f, 0.f, 0.f, 0.f);
            if (row < NN)
                v = *(const float4*)(x + (size_t)row * NF + c * BK + c4 * 4);
            __nv_bfloat16 h0 = __float2bfloat16(v.x);
            __nv_bfloat16 h1 = __float2bfloat16(v.y);
            __nv_bfloat16 h2 = __float2bfloat16(v.z);
            __nv_bfloat16 h3 = __float2bfloat16(v.w);
            __nv_bfloat16 l0 = __float2bfloat16(v.x - __bfloat162float(h0));
            __nv_bfloat16 l1 = __float2bfloat16(v.y - __bfloat162float(h1));
            __nv_bfloat16 l2 = __float2bfloat16(v.z - __bfloat162float(h2));
            __nv_bfloat16 l3 = __float2bfloat16(v.w - __bfloat162float(h3));
            __nv_bfloat162 ha, hb, la, lb;
            ha.x = h0; ha.y = h1; hb.x = h2; hb.y = h3;
            la.x = l0; la.y = l1; lb.x = l2; lb.y = l3;
            uint32_t off = (uint32_t)(r * (LDA * 2) + c4 * 8);
            asm volatile("st.shared.v2.b32 [%0], {%1, %2};"
                         :: "r"(sb + SA_HI + off),
                            "r"(*(uint32_t*)&ha), "r"(*(uint32_t*)&hb));
            asm volatile("st.shared.v2.b32 [%0], {%1, %2};"
                         :: "r"(sb + SA_LO + off),
                            "r"(*(uint32_t*)&la), "r"(*(uint32_t*)&lb));
        }
        // ---- B tile: W1t hi/lo, 128 n x 64 k bf16 ----
#pragma unroll
        for (int it = 0; it < 4; it++) {
            int idx = it * 256 + tid;          // 0..1023
            int n = idx >> 3, g = idx & 7;
            uint4 vh = *(const uint4*)(Bhi + (size_t)n * NF + c * BK + g * 8);
            uint4 vl = *(const uint4*)(Blo + (size_t)n * NF + c * BK + g * 8);
            uint32_t off = (uint32_t)(n * (LDA * 2) + g * 16);
            asm volatile("st.shared.v4.b32 [%0], {%1,%2,%3,%4};"
                         :: "r"(sb + SB_HI + off), "r"(vh.x), "r"(vh.y), "r"(vh.z), "r"(vh.w));
            asm volatile("st.shared.v4.b32 [%0], {%1,%2,%3,%4};"
                         :: "r"(sb + SB_LO + off), "r"(vl.x), "r"(vl.y), "r"(vl.z), "r"(vl.w));
        }
        __syncthreads();

        // ---- compute: 4 k-steps of 16 ----
#pragma unroll
        for (int ks = 0; ks < 4; ks++) {
            uint32_t ah[4][4], al[4][4];
#pragma unroll
            for (int mi = 0; mi < 4; mi++) {
                uint32_t aa = a_base + (uint32_t)(mi * 16 * (LDA * 2) + ks * 32);
                ldsm_x4(ah[mi], aa);
                ldsm_x4(al[mi], aa + (uint32_t)(SA_LO - SA_HI));
            }
#pragma unroll
            for (int ni = 0; ni < 4; ni++) {
                uint32_t ba = b_base + (uint32_t)(ni * 8 * (LDA * 2) + ks * 32);
                uint32_t bh[2], bl[2];
                ldsm_x2(bh, ba);
                ldsm_x2(bl, ba + (uint32_t)(SB_LO - SB_HI));
#pragma unroll
                for (int mi = 0; mi < 4; mi++) {
                    mma_bf16(acc[mi][ni], ah[mi], bh);
                    mma_bf16(acc[mi][ni], al[mi], bh);
                    mma_bf16(acc[mi][ni], ah[mi], bl);
                }
            }
        }
    }

    // ---- epilogue: write fp32 result ----
    const int rbase = m0 + wm * 64 + (lane >> 2);
    const int cbase = wn * 32 + 2 * (lane & 3);
#pragma unroll
    for (int mi = 0; mi < 4; mi++) {
        int r0 = rbase + mi * 16;
        int r1 = r0 + 8;
#pragma unroll
        for (int ni = 0; ni < 4; ni++) {
            int col = cbase + ni * 8;
            if (r0 < NN)
                *(float2*)(s1 + (size_t)r0 * NH + col) =
                    make_float2(acc[mi][ni][0], acc[mi][ni][1]);
            if (r1 < NN)
                *(float2*)(s1 + (size_t)r1 * NH + col) =
                    make_float2(acc[mi][ni][2], acc[mi][ni][3]);
        }
    }
}

// ---------------- CSR gather aggregation ----------------
template <int F4, bool RELU>
__global__ void k_agg(const float* __restrict__ src, const float* __restrict__ bias,
                      float* __restrict__ out) {
    int idx = blockIdx.x * blockDim.x + threadIdx.x;
    int n = idx / F4;
    int f = idx % F4;
    if (n >= NN) return;
    int beg = g_rowptr[n], end = g_rowptr[n + 1];
    const float4* s4 = (const float4*)src;
    float4 acc = make_float4(0.f, 0.f, 0.f, 0.f);
    int e = beg;
    for (; e + 1 < end; e += 2) {
        int   c0 = g_col[e],     c1 = g_col[e + 1];
        float w0 = g_val[e],     w1 = g_val[e + 1];
        float4 v0 = s4[(size_t)c0 * F4 + f];
        float4 v1 = s4[(size_t)c1 * F4 + f];
        acc.x = fmaf(v0.x, w0, acc.x); acc.y = fmaf(v0.y, w0, acc.y);
        acc.z = fmaf(v0.z, w0, acc.z); acc.w = fmaf(v0.w, w0, acc.w);
        acc.x = fmaf(v1.x, w1, acc.x); acc.y = fmaf(v1.y, w1, acc.y);
        acc.z = fmaf(v1.z, w1, acc.z); acc.w = fmaf(v1.w, w1, acc.w);
    }
    if (e < end) {
        int c = g_col[e]; float w = g_val[e];
        float4 v = s4[(size_t)c * F4 + f];
        acc.x = fmaf(v.x, w, acc.x); acc.y = fmaf(v.y, w, acc.y);
        acc.z = fmaf(v.z, w, acc.z); acc.w = fmaf(v.w, w, acc.w);
    }
    float4 b = ((const float4*)bias)[f];
    acc.x += b.x; acc.y += b.y; acc.z += b.z; acc.w += b.w;
    if (RELU) {
        acc.x = fmaxf(acc.x, 0.f); acc.y = fmaxf(acc.y, 0.f);
        acc.z = fmaxf(acc.z, 0.f); acc.w = fmaxf(acc.w, 0.f);
    }
    ((float4*)out)[(size_t)n * F4 + f] = acc;
}

// ---------------- GEMM2: s2 = h @ W2  (scalar FFMA, W2 in smem) ----------------
__global__ __launch_bounds__(256) void k_gemm2(const float* __restrict__ h,
                                               const float* __restrict__ W2,
                                               float* __restrict__ s2) {
    __shared__ __align__(16) float Ws[NH * NC];
    __shared__ __align__(16) float Hs[16][264];
    const int tid = threadIdx.x;
    const int n0  = blockIdx.x * 256;
#pragma unroll
    for (int i = 0; i < 5; i++) {
        int fi = tid + i * 256;
        *(float4*)&Ws[fi * 4] = *(const float4*)(W2 + (size_t)fi * 4);
    }
    const int tc = tid & 7;
    const int tr = tid >> 3;
    const int r0 = tr * 8;
    const int c0 = tc * 5;
    float acc[8][5];
#pragma unroll
    for (int i = 0; i < 8; i++)
#pragma unroll
        for (int j = 0; j < 5; j++) acc[i][j] = 0.f;

    for (int kc = 0; kc < NH; kc += 16) {
        __syncthreads();
#pragma unroll
        for (int i = 0; i < 4; i++) {
            int fi = tid + i * 256;
            int r = fi >> 2, c4 = fi & 3;
            int n = n0 + r;
            float4 v = make_float4(0.f, 0.f, 0.f, 0.f);
            if (n < NN)
                v = *(const float4*)(h + (size_t)n * NH + kc + c4 * 4);
            Hs[c4 * 4 + 0][r] = v.x;
            Hs[c4 * 4 + 1][r] = v.y;
            Hs[c4 * 4 + 2][r] = v.z;
            Hs[c4 * 4 + 3][r] = v.w;
        }
        __syncthreads();
#pragma unroll
        for (int k = 0; k < 16; k++) {
            float4 a0 = *(const float4*)&Hs[k][r0];
            float4 a1 = *(const float4*)&Hs[k][r0 + 4];
            float a[8] = {a0.x, a0.y, a0.z, a0.w, a1.x, a1.y, a1.z, a1.w};
            float w[5];
#pragma unroll
            for (int j = 0; j < 5; j++) w[j] = Ws[(kc + k) * NC + c0 + j];
#pragma unroll
            for (int i = 0; i < 8; i++)
#pragma unroll
                for (int j = 0; j < 5; j++) acc[i][j] = fmaf(a[i], w[j], acc[i][j]);
        }
    }
#pragma unroll
    for (int i = 0; i < 8; i++) {
        int n = n0 + r0 + i;
        if (n < NN) {
#pragma unroll
            for (int j = 0; j < 5; j++) s2[(size_t)n * NC + c0 + j] = acc[i][j];
        }
    }
}

// ---------------- launcher ----------------
extern "C" void kernel_launch(void* const* d_in, const int* in_sizes, int n_in,
                              void* d_out, int out_size) {
    const float* x  = (const float*)d_in[0];
    const int*   es = (const int*)d_in[1];
    const int*   ed = (const int*)d_in[2];
    const float* ew = (const float*)d_in[3];
    const float* W1 = (const float*)d_in[4];
    const float* b1 = (const float*)d_in[5];
    const float* W2 = (const float*)d_in[6];
    const float* b2 = (const float*)d_in[7];
    float* out = (float*)d_out;

    float *s1p, *hp, *s2p;
    cudaGetSymbolAddress((void**)&s1p, g_s1);
    cudaGetSymbolAddress((void**)&hp,  g_h);
    cudaGetSymbolAddress((void**)&s2p, g_s2);

    cudaFuncSetAttribute(k_gemm1_mma, cudaFuncAttributeMaxDynamicSharedMemorySize,
                         SMEM_SZ);

    // CSR build + W1 split
    k_zero<<<(NN + 255) / 256, 256>>>();
    k_count<<<(NE + 255) / 256, 256>>>(ed);
    k_w1split<<<(NF * NH + 255) / 256, 256>>>(W1);
    k_blocksum<<<(NN + 1023) / 1024, 1024>>>();
    k_scanbsum<<<1, 64>>>();
    k_scanwrite<<<(NN + 1023) / 1024, 1024>>>();
    k_fill<<<(NE + 255) / 256, 256>>>(es, ed, ew);

    // layer 1
    k_gemm1_mma<<<(NN + 127) / 128, 256, SMEM_SZ>>>(x, s1p);
    k_agg<32, true><<<(NN * 32 + 255) / 256, 256>>>(s1p, b1, hp);

    // layer 2
    k_gemm2<<<(NN + 255) / 256, 256>>>(hp, W2, s2p);
    k_agg<10, false><<<(NN * 10 + 255) / 256, 256>>>(s2p, b2, out);
}

// round 4
// speedup vs baseline: 1.6224x; 1.1666x over previous
#include <cuda_runtime.h>
#include <cuda_bf16.h>
#include <cstdint>

#define NN 50000
#define NE 800000
#define NF 512
#define NH 128
#define NC 40

// ---------------- scratch (device globals; no allocation allowed) ----------------
__device__ float g_s1[(size_t)NN * NH];     // x @ W1
__device__ float g_s2[(size_t)NN * NC];     // h @ W2
__device__ __nv_bfloat16 g_h_hi[(size_t)NN * NH];  // relu(agg1+b1) hi
__device__ __nv_bfloat16 g_h_lo[(size_t)NN * NH];  // relu(agg1+b1) lo
__device__ int   g_rowptr[NN + 1];
__device__ int   g_deg[NN];
__device__ int   g_cursor[NN];
__device__ int   g_col[NE];
__device__ float g_val[NE];
__device__ int   g_bsum[64];
__device__ __nv_bfloat16 g_w1t_hi[(size_t)NH * NF];   // W1^T hi: [n][k]
__device__ __nv_bfloat16 g_w1t_lo[(size_t)NH * NF];   // W1^T lo: [n][k]
__device__ __nv_bfloat16 g_w2t_hi[(size_t)NC * NH];   // W2^T hi: [n][k]
__device__ __nv_bfloat16 g_w2t_lo[(size_t)NC * NH];   // W2^T lo: [n][k]

// ---------------- PTX helpers (portable: sm_80-level only) ----------------
__device__ __forceinline__ uint32_t smem_u32(const void* p) {
    uint32_t a;
    asm("{ .reg .u64 t; cvta.to.shared.u64 t, %1; cvt.u32.u64 %0, t; }"
        : "=r"(a) : "l"(p));
    return a;
}
__device__ __forceinline__ void ldsm_x4(uint32_t* r, uint32_t addr) {
    asm volatile("ldmatrix.sync.aligned.m8n8.x4.shared.b16 {%0,%1,%2,%3}, [%4];"
                 : "=r"(r[0]), "=r"(r[1]), "=r"(r[2]), "=r"(r[3]) : "r"(addr));
}
__device__ __forceinline__ void ldsm_x2(uint32_t* r, uint32_t addr) {
    asm volatile("ldmatrix.sync.aligned.m8n8.x2.shared.b16 {%0,%1}, [%2];"
                 : "=r"(r[0]), "=r"(r[1]) : "r"(addr));
}
__device__ __forceinline__ void mma_bf16(float* c, const uint32_t* a, const uint32_t* b) {
    asm volatile(
        "mma.sync.aligned.m16n8k16.row.col.f32.bf16.bf16.f32 "
        "{%0,%1,%2,%3}, {%4,%5,%6,%7}, {%8,%9}, {%0,%1,%2,%3};"
        : "+f"(c[0]), "+f"(c[1]), "+f"(c[2]), "+f"(c[3])
        : "r"(a[0]), "r"(a[1]), "r"(a[2]), "r"(a[3]), "r"(b[0]), "r"(b[1]));
}

// ---------------- CSR build ----------------
__global__ void k_zero() {
    int i = blockIdx.x * blockDim.x + threadIdx.x;
    if (i < NN) { g_deg[i] = 0; g_cursor[i] = 0; }
}
__global__ void k_count(const int* __restrict__ dst) {
    int e = blockIdx.x * blockDim.x + threadIdx.x;
    if (e < NE) atomicAdd(&g_deg[dst[e]], 1);
}
__global__ void k_blocksum() {
    __shared__ int sh[1024];
    int t = threadIdx.x;
    int i = blockIdx.x * 1024 + t;
    sh[t] = (i < NN) ? g_deg[i] : 0;
    __syncthreads();
    for (int off = 512; off > 0; off >>= 1) {
        if (t < off) sh[t] += sh[t + off];
        __syncthreads();
    }
    if (t == 0) g_bsum[blockIdx.x] = sh[0];
}
__global__ void k_scanbsum() {
    __shared__ int sh[64];
    const int nb = (NN + 1023) / 1024;
    int t = threadIdx.x;
    int v = (t < nb) ? g_bsum[t] : 0;
    sh[t] = v;
    __syncthreads();
    for (int off = 1; off < 64; off <<= 1) {
        int u = (t >= off) ? sh[t - off] : 0;
        __syncthreads();
        sh[t] += u;
        __syncthreads();
    }
    g_bsum[t] = sh[t] - v;
    if (t == nb - 1) g_rowptr[NN] = sh[t];
}
__global__ void k_scanwrite() {
    __shared__ int sh[1024];
    int t = threadIdx.x;
    int i = blockIdx.x * 1024 + t;
    int v = (i < NN) ? g_deg[i] : 0;
    sh[t] = v;
    __syncthreads();
    for (int off = 1; off < 1024; off <<= 1) {
        int u = (t >= off) ? sh[t - off] : 0;
        __syncthreads();
        sh[t] += u;
        __syncthreads();
    }
    if (i < NN) g_rowptr[i] = g_bsum[blockIdx.x] + sh[t] - v;
}
__global__ void k_fill(const int* __restrict__ src, const int* __restrict__ dst,
                       const float* __restrict__ w) {
    int e = blockIdx.x * blockDim.x + threadIdx.x;
    if (e < NE) {
        int d = dst[e];
        int pos = g_rowptr[d] + atomicAdd(&g_cursor[d], 1);
        g_col[pos] = src[e];
        g_val[pos] = w[e];
    }
}

// ---------------- weight transpose + hi/lo split ----------------
__global__ void k_w1split(const float* __restrict__ W1) {
    int idx = blockIdx.x * blockDim.x + threadIdx.x;   // over NF*NH
    if (idx < NF * NH) {
        int k = idx >> 7;
        int n = idx & 127;
        float v = W1[idx];
        __nv_bfloat16 hi = __float2bfloat16(v);
        __nv_bfloat16 lo = __float2bfloat16(v - __bfloat162float(hi));
        g_w1t_hi[(size_t)n * NF + k] = hi;
        g_w1t_lo[(size_t)n * NF + k] = lo;
    }
}
__global__ void k_w2split(const float* __restrict__ W2) {
    int idx = blockIdx.x * blockDim.x + threadIdx.x;   // over NH*NC
    if (idx < NH * NC) {
        int k = idx / NC;
        int n = idx % NC;
        float v = W2[idx];
        __nv_bfloat16 hi = __float2bfloat16(v);
        __nv_bfloat16 lo = __float2bfloat16(v - __bfloat162float(hi));
        g_w2t_hi[(size_t)n * NH + k] = hi;
        g_w2t_lo[(size_t)n * NH + k] = lo;
    }
}

// ---------------- GEMM1: s1 = x @ W1 via mma.sync bf16 split (3 MMA) ----------
#define BK      64
#define NCHUNK  (NF / BK)          // 8
#define LDA     72                 // bf16 elems per smem row (144 B)
#define PLANE   (128 * LDA * 2)    // 18432 B
#define SA_HI   0
#define SA_LO   PLANE
#define SB_HI   (2 * PLANE)
#define SB_LO   (3 * PLANE)
#define SMEM_SZ (4 * PLANE)        // 73728 B

__global__ __launch_bounds__(256) void k_gemm1_mma(const float* __restrict__ x,
                                                   float* __restrict__ s1) {
    extern __shared__ __align__(16) char smem[];
    const uint32_t sb = smem_u32(smem);
    const int tid = threadIdx.x;
    const int lane = tid & 31;
    const int wid = tid >> 5;
    const int wm = wid >> 2;
    const int wn = wid & 3;
    const int m0 = blockIdx.x * 128;

    const __nv_bfloat16* __restrict__ Bhi = g_w1t_hi;
    const __nv_bfloat16* __restrict__ Blo = g_w1t_lo;

    float acc[4][4][4];
#pragma unroll
    for (int i = 0; i < 4; i++)
#pragma unroll
        for (int j = 0; j < 4; j++)
#pragma unroll
            for (int q = 0; q < 4; q++) acc[i][j][q] = 0.f;

    const uint32_t a_base = sb + SA_HI +
        (uint32_t)(wm * 64 + (lane & 15)) * (LDA * 2) + (uint32_t)((lane >> 4) * 16);
    const uint32_t b_base = sb + SB_HI +
        (uint32_t)(wn * 32 + (lane & 7)) * (LDA * 2) + (uint32_t)(((lane >> 3) & 1) * 16);

    for (int c = 0; c < NCHUNK; c++) {
        if (c > 0) __syncthreads();
#pragma unroll
        for (int it = 0; it < 8; it++) {
            int idx = it * 256 + tid;
            int r = idx >> 4, c4 = idx & 15;
            int row = m0 + r;
            float4 v = make_float4(0.f, 0.f, 0.f, 0.f);
            if (row < NN)
                v = *(const float4*)(x + (size_t)row * NF + c * BK + c4 * 4);
            __nv_bfloat16 h0 = __float2bfloat16(v.x);
            __nv_bfloat16 h1 = __float2bfloat16(v.y);
            __nv_bfloat16 h2 = __float2bfloat16(v.z);
            __nv_bfloat16 h3 = __float2bfloat16(v.w);
            __nv_bfloat16 l0 = __float2bfloat16(v.x - __bfloat162float(h0));
            __nv_bfloat16 l1 = __float2bfloat16(v.y - __bfloat162float(h1));
            __nv_bfloat16 l2 = __float2bfloat16(v.z - __bfloat162float(h2));
            __nv_bfloat16 l3 = __float2bfloat16(v.w - __bfloat162float(h3));
            __nv_bfloat162 ha, hb, la, lb;
            ha.x = h0; ha.y = h1; hb.x = h2; hb.y = h3;
            la.x = l0; la.y = l1; lb.x = l2; lb.y = l3;
            uint32_t off = (uint32_t)(r * (LDA * 2) + c4 * 8);
            asm volatile("st.shared.v2.b32 [%0], {%1, %2};"
                         :: "r"(sb + SA_HI + off),
                            "r"(*(uint32_t*)&ha), "r"(*(uint32_t*)&hb));
            asm volatile("st.shared.v2.b32 [%0], {%1, %2};"
                         :: "r"(sb + SA_LO + off),
                            "r"(*(uint32_t*)&la), "r"(*(uint32_t*)&lb));
        }
#pragma unroll
        for (int it = 0; it < 4; it++) {
            int idx = it * 256 + tid;
            int n = idx >> 3, g = idx & 7;
            uint4 vh = *(const uint4*)(Bhi + (size_t)n * NF + c * BK + g * 8);
            uint4 vl = *(const uint4*)(Blo + (size_t)n * NF + c * BK + g * 8);
            uint32_t off = (uint32_t)(n * (LDA * 2) + g * 16);
            asm volatile("st.shared.v4.b32 [%0], {%1,%2,%3,%4};"
                         :: "r"(sb + SB_HI + off), "r"(vh.x), "r"(vh.y), "r"(vh.z), "r"(vh.w));
            asm volatile("st.shared.v4.b32 [%0], {%1,%2,%3,%4};"
                         :: "r"(sb + SB_LO + off), "r"(vl.x), "r"(vl.y), "r"(vl.z), "r"(vl.w));
        }
        __syncthreads();

#pragma unroll
        for (int ks = 0; ks < 4; ks++) {
            uint32_t ah[4][4], al[4][4];
#pragma unroll
            for (int mi = 0; mi < 4; mi++) {
                uint32_t aa = a_base + (uint32_t)(mi * 16 * (LDA * 2) + ks * 32);
                ldsm_x4(ah[mi], aa);
                ldsm_x4(al[mi], aa + (uint32_t)(SA_LO - SA_HI));
            }
#pragma unroll
            for (int ni = 0; ni < 4; ni++) {
                uint32_t ba = b_base + (uint32_t)(ni * 8 * (LDA * 2) + ks * 32);
                uint32_t bh[2], bl[2];
                ldsm_x2(bh, ba);
                ldsm_x2(bl, ba + (uint32_t)(SB_LO - SB_HI));
#pragma unroll
                for (int mi = 0; mi < 4; mi++) {
                    mma_bf16(acc[mi][ni], ah[mi], bh);
                    mma_bf16(acc[mi][ni], al[mi], bh);
                    mma_bf16(acc[mi][ni], ah[mi], bl);
                }
            }
        }
    }

    const int rbase = m0 + wm * 64 + (lane >> 2);
    const int cbase = wn * 32 + 2 * (lane & 3);
#pragma unroll
    for (int mi = 0; mi < 4; mi++) {
        int r0 = rbase + mi * 16;
        int r1 = r0 + 8;
#pragma unroll
        for (int ni = 0; ni < 4; ni++) {
            int col = cbase + ni * 8;
            if (r0 < NN)
                *(float2*)(s1 + (size_t)r0 * NH + col) =
                    make_float2(acc[mi][ni][0], acc[mi][ni][1]);
            if (r1 < NN)
                *(float2*)(s1 + (size_t)r1 * NH + col) =
                    make_float2(acc[mi][ni][2], acc[mi][ni][3]);
        }
    }
}

// ---------------- agg layer 1: gather + bias + relu -> bf16 hi/lo ----------------
__global__ void k_agg1(const float* __restrict__ src, const float* __restrict__ bias) {
    int idx = blockIdx.x * blockDim.x + threadIdx.x;
    int n = idx >> 5;           // 32 threads per node (NH/4)
    int f = idx & 31;
    if (n >= NN) return;
    int beg = g_rowptr[n], end = g_rowptr[n + 1];
    const float4* s4 = (const float4*)src;
    float4 acc = make_float4(0.f, 0.f, 0.f, 0.f);
    int e = beg;
    for (; e + 1 < end; e += 2) {
        int   c0 = g_col[e],     c1 = g_col[e + 1];
        float w0 = g_val[e],     w1 = g_val[e + 1];
        float4 v0 = s4[(size_t)c0 * 32 + f];
        float4 v1 = s4[(size_t)c1 * 32 + f];
        acc.x = fmaf(v0.x, w0, acc.x); acc.y = fmaf(v0.y, w0, acc.y);
        acc.z = fmaf(v0.z, w0, acc.z); acc.w = fmaf(v0.w, w0, acc.w);
        acc.x = fmaf(v1.x, w1, acc.x); acc.y = fmaf(v1.y, w1, acc.y);
        acc.z = fmaf(v1.z, w1, acc.z); acc.w = fmaf(v1.w, w1, acc.w);
    }
    if (e < end) {
        int c = g_col[e]; float w = g_val[e];
        float4 v = s4[(size_t)c * 32 + f];
        acc.x = fmaf(v.x, w, acc.x); acc.y = fmaf(v.y, w, acc.y);
        acc.z = fmaf(v.z, w, acc.z); acc.w = fmaf(v.w, w, acc.w);
    }
    float4 b = ((const float4*)bias)[f];
    acc.x = fmaxf(acc.x + b.x, 0.f);
    acc.y = fmaxf(acc.y + b.y, 0.f);
    acc.z = fmaxf(acc.z + b.z, 0.f);
    acc.w = fmaxf(acc.w + b.w, 0.f);
    // split to bf16 hi/lo
    __nv_bfloat162 h01, h23, l01, l23;
    h01.x = __float2bfloat16(acc.x); h01.y = __float2bfloat16(acc.y);
    h23.x = __float2bfloat16(acc.z); h23.y = __float2bfloat16(acc.w);
    l01.x = __float2bfloat16(acc.x - __bfloat162float(h01.x));
    l01.y = __float2bfloat16(acc.y - __bfloat162float(h01.y));
    l23.x = __float2bfloat16(acc.z - __bfloat162float(h23.x));
    l23.y = __float2bfloat16(acc.w - __bfloat162float(h23.y));
    uint2 hv = make_uint2(*(uint32_t*)&h01, *(uint32_t*)&h23);
    uint2 lv = make_uint2(*(uint32_t*)&l01, *(uint32_t*)&l23);
    *(uint2*)(g_h_hi + (size_t)n * NH + f * 4) = hv;
    *(uint2*)(g_h_lo + (size_t)n * NH + f * 4) = lv;
}

// ---------------- agg layer 2: gather + bias -> fp32 out ----------------
__global__ void k_agg2(const float* __restrict__ src, const float* __restrict__ bias,
                       float* __restrict__ out) {
    int idx = blockIdx.x * blockDim.x + threadIdx.x;
    int n = idx / 10;           // 10 threads per node (NC/4)
    int f = idx % 10;
    if (n >= NN) return;
    int beg = g_rowptr[n], end = g_rowptr[n + 1];
    const float4* s4 = (const float4*)src;
    float4 acc = make_float4(0.f, 0.f, 0.f, 0.f);
    int e = beg;
    for (; e + 1 < end; e += 2) {
        int   c0 = g_col[e],     c1 = g_col[e + 1];
        float w0 = g_val[e],     w1 = g_val[e + 1];
        float4 v0 = s4[(size_t)c0 * 10 + f];
        float4 v1 = s4[(size_t)c1 * 10 + f];
        acc.x = fmaf(v0.x, w0, acc.x); acc.y = fmaf(v0.y, w0, acc.y);
        acc.z = fmaf(v0.z, w0, acc.z); acc.w = fmaf(v0.w, w0, acc.w);
        acc.x = fmaf(v1.x, w1, acc.x); acc.y = fmaf(v1.y, w1, acc.y);
        acc.z = fmaf(v1.z, w1, acc.z); acc.w = fmaf(v1.w, w1, acc.w);
    }
    if (e < end) {
        int c = g_col[e]; float w = g_val[e];
        float4 v = s4[(size_t)c * 10 + f];
        acc.x = fmaf(v.x, w, acc.x); acc.y = fmaf(v.y, w, acc.y);
        acc.z = fmaf(v.z, w, acc.z); acc.w = fmaf(v.w, w, acc.w);
    }
    float4 b = ((const float4*)bias)[f];
    acc.x += b.x; acc.y += b.y; acc.z += b.z; acc.w += b.w;
    ((float4*)out)[(size_t)n * 10 + f] = acc;
}

// ---------------- GEMM2: s2 = h @ W2 via mma.sync bf16 split ----------------
// CTA 128 rows, N=40, K=128 fully resident. 256 threads = 8 warps, warp=16 rows.
#define LDA2    136                        // bf16 per smem row (272 B)
#define APL     (128 * LDA2 * 2)           // 34816 B
#define BPL     (40 * LDA2 * 2)            // 10880 B
#define S2A_HI  0
#define S2A_LO  APL
#define S2B_HI  (2 * APL)
#define S2B_LO  (2 * APL + BPL)
#define SMEM2_SZ (2 * APL + 2 * BPL)       // 91392 B

__global__ __launch_bounds__(256) void k_gemm2_mma(float* __restrict__ s2) {
    extern __shared__ __align__(16) char smem[];
    const uint32_t sb = smem_u32(smem);
    const int tid = threadIdx.x;
    const int lane = tid & 31;
    const int wid = tid >> 5;
    const int n0 = blockIdx.x * 128;

    // load A planes (h hi/lo): 128 rows x 128 k bf16 each
#pragma unroll
    for (int it = 0; it < 8; it++) {
        int idx = it * 256 + tid;              // 2048 uint4 per plane
        int r = idx >> 4, g = idx & 15;
        int row = n0 + r;
        uint4 vh = make_uint4(0, 0, 0, 0), vl = make_uint4(0, 0, 0, 0);
        if (row < NN) {
            vh = *(const uint4*)(g_h_hi + (size_t)row * NH + g * 8);
            vl = *(const uint4*)(g_h_lo + (size_t)row * NH + g * 8);
        }
        uint32_t off = (uint32_t)(r * (LDA2 * 2) + g * 16);
        asm volatile("st.shared.v4.b32 [%0], {%1,%2,%3,%4};"
                     :: "r"(sb + S2A_HI + off), "r"(vh.x), "r"(vh.y), "r"(vh.z), "r"(vh.w));
        asm volatile("st.shared.v4.b32 [%0], {%1,%2,%3,%4};"
                     :: "r"(sb + S2A_LO + off), "r"(vl.x), "r"(vl.y), "r"(vl.z), "r"(vl.w));
    }
    // load B planes (W2^T hi/lo): 40 rows x 128 k bf16 each
#pragma unroll
    for (int it = 0; it < 3; it++) {
        int idx = it * 256 + tid;              // 640 uint4 per plane
        if (idx < 40 * 8) {
            int r = idx >> 3, g = idx & 7;     // hmm 128 bf16 = 16 uint4/row
            (void)r; (void)g;
        }
        if (idx < 640) {
            int r = idx >> 4, g = idx & 15;
            uint4 vh = *(const uint4*)(g_w2t_hi + (size_t)r * NH + g * 8);
            uint4 vl = *(const uint4*)(g_w2t_lo + (size_t)r * NH + g * 8);
            uint32_t off = (uint32_t)(r * (LDA2 * 2) + g * 16);
            asm volatile("st.shared.v4.b32 [%0], {%1,%2,%3,%4};"
                         :: "r"(sb + S2B_HI + off), "r"(vh.x), "r"(vh.y), "r"(vh.z), "r"(vh.w));
            asm volatile("st.shared.v4.b32 [%0], {%1,%2,%3,%4};"
                         :: "r"(sb + S2B_LO + off), "r"(vl.x), "r"(vl.y), "r"(vl.z), "r"(vl.w));
        }
    }
    __syncthreads();

    float acc[5][4];
#pragma unroll
    for (int i = 0; i < 5; i++)
#pragma unroll
        for (int q = 0; q < 4; q++) acc[i][q] = 0.f;

    const uint32_t a_base = sb + S2A_HI +
        (uint32_t)(wid * 16 + (lane & 15)) * (LDA2 * 2) + (uint32_t)((lane >> 4) * 16);
    const uint32_t b_base = sb + S2B_HI +
        (uint32_t)(lane & 7) * (LDA2 * 2) + (uint32_t)(((lane >> 3) & 1) * 16);

#pragma unroll
    for (int ks = 0; ks < 8; ks++) {
        uint32_t ah[4], al[4];
        uint32_t aa = a_base + (uint32_t)(ks * 32);
        ldsm_x4(ah, aa);
        ldsm_x4(al, aa + (uint32_t)(S2A_LO - S2A_HI));
#pragma unroll
        for (int nt = 0; nt < 5; nt++) {
            uint32_t ba = b_base + (uint32_t)(nt * 8 * (LDA2 * 2) + ks * 32);
            uint32_t bh[2], bl[2];
            ldsm_x2(bh, ba);
            ldsm_x2(bl, ba + (uint32_t)(S2B_LO - S2B_HI));
            mma_bf16(acc[nt], ah, bh);
            mma_bf16(acc[nt], al, bh);
            mma_bf16(acc[nt], ah, bl);
        }
    }

    const int r0 = n0 + wid * 16 + (lane >> 2);
    const int r1 = r0 + 8;
    const int cb = 2 * (lane & 3);
#pragma unroll
    for (int nt = 0; nt < 5; nt++) {
        int col = cb + nt * 8;
        if (r0 < NN)
            *(float2*)(s2 + (size_t)r0 * NC + col) = make_float2(acc[nt][0], acc[nt][1]);
        if (r1 < NN)
            *(float2*)(s2 + (size_t)r1 * NC + col) = make_float2(acc[nt][2], acc[nt][3]);
    }
}

// ---------------- launcher with capture fork/join ----------------
extern "C" void kernel_launch(void* const* d_in, const int* in_sizes, int n_in,
                              void* d_out, int out_size) {
    const float* x  = (const float*)d_in[0];
    const int*   es = (const int*)d_in[1];
    const int*   ed = (const int*)d_in[2];
    const float* ew = (const float*)d_in[3];
    const float* W1 = (const float*)d_in[4];
    const float* b1 = (const float*)d_in[5];
    const float* W2 = (const float*)d_in[6];
    const float* b2 = (const float*)d_in[7];
    float* out = (float*)d_out;

    float *s1p, *s2p;
    cudaGetSymbolAddress((void**)&s1p, g_s1);
    cudaGetSymbolAddress((void**)&s2p, g_s2);

    cudaFuncSetAttribute(k_gemm1_mma, cudaFuncAttributeMaxDynamicSharedMemorySize, SMEM_SZ);
    cudaFuncSetAttribute(k_gemm2_mma, cudaFuncAttributeMaxDynamicSharedMemorySize, SMEM2_SZ);

    // lazily created side stream + events (resources only; identical work per call)
    static cudaStream_t s2s = nullptr;
    static cudaEvent_t eFork = nullptr, eCSR = nullptr;
    if (!s2s) {
        cudaStreamCreateWithFlags(&s2s, cudaStreamNonBlocking);
        cudaEventCreateWithFlags(&eFork, cudaEventDisableTiming);
        cudaEventCreateWithFlags(&eCSR, cudaEventDisableTiming);
    }

    // fork: CSR build chain on side stream
    cudaEventRecord(eFork, 0);
    cudaStreamWaitEvent(s2s, eFork, 0);
    k_zero<<<(NN + 255) / 256, 256, 0, s2s>>>();
    k_count<<<(NE + 255) / 256, 256, 0, s2s>>>(ed);
    k_blocksum<<<(NN + 1023) / 1024, 1024, 0, s2s>>>();
    k_scanbsum<<<1, 64, 0, s2s>>>();
    k_scanwrite<<<(NN + 1023) / 1024, 1024, 0, s2s>>>();
    k_fill<<<(NE + 255) / 256, 256, 0, s2s>>>(es, ed, ew);
    cudaEventRecord(eCSR, s2s);

    // main stream: weight prep + GEMM1 (independent of CSR)
    k_w1split<<<(NF * NH + 255) / 256, 256>>>(W1);
    k_w2split<<<(NH * NC + 255) / 256, 256>>>(W2);
    k_gemm1_mma<<<(NN + 127) / 128, 256, SMEM_SZ>>>(x, s1p);

    // join, then the dependent tail
    cudaStreamWaitEvent(0, eCSR, 0);
    k_agg1<<<(NN * 32 + 255) / 256, 256>>>(s1p, b1);
    k_gemm2_mma<<<(NN + 127) / 128, 256, SMEM2_SZ>>>(s2p);
    k_agg2<<<(NN * 10 + 255) / 256, 256>>>(s2p, b2, out);
}